// round 1
// baseline (speedup 1.0000x reference)
#include <cuda_runtime.h>

// ----------------------------------------------------------------------------
// VQExpert: z_e [16,2048,512] f32, codebook [8192,512] f32.
// Out (f32, concatenated): z_q_st [16*2048*512] | indices [16*2048] | vq_loss [1]
//
// dist[m][n] = (z_sq[m] + e_sq[n]) - 2 * dot(z[m], e[n])   (replicates ref fp32 order)
// argmin over n (lowest index on ties), z_q_st = z_e + (z_q - z_e),
// vq_loss = 1.25 * mean((z_q - z_e)^2) / 512.
// ----------------------------------------------------------------------------

#define KDIM  512
#define MAX_M 32768
#define MAX_N 8192

// Scratch (no device allocation allowed -> __device__ globals)
__device__ unsigned long long g_best[MAX_M];
__device__ float g_zsq[MAX_M];
__device__ float g_esq[MAX_N];
__device__ float g_partials[MAX_M];

// ---------------------------------------------------------------- row sumsq
__global__ void rowsq_kernel(const float* __restrict__ x, int K, int which)
{
    int row = blockIdx.x;
    const float* xr = x + (size_t)row * K;
    float s = 0.f;
    for (int c = threadIdx.x; c < K; c += 128) { float v = xr[c]; s += v * v; }
    #pragma unroll
    for (int o = 16; o; o >>= 1) s += __shfl_down_sync(0xffffffffu, s, o);
    __shared__ float ws[4];
    if ((threadIdx.x & 31) == 0) ws[threadIdx.x >> 5] = s;
    __syncthreads();
    if (threadIdx.x == 0) {
        float t = ws[0] + ws[1] + ws[2] + ws[3];
        if (which) g_esq[row] = t; else g_zsq[row] = t;
    }
}

// ---------------------------------------------------------------- init best
__global__ void init_best_kernel(int M)
{
    int i = blockIdx.x * blockDim.x + threadIdx.x;
    if (i < M) g_best[i] = 0xFFFFFFFFFFFFFFFFull;
}

// ---------------------------------------------------------------- GEMM+argmin
#define BM 128
#define BN 128
#define BK 16
#define BMP (BM + 4)
#define BNP (BN + 4)

__global__ __launch_bounds__(256)
void gemm_argmin_kernel(const float* __restrict__ A,   // [M,K] z_flat
                        const float* __restrict__ B,   // [N,K] codebook
                        int K)
{
    __shared__ float As[2][BK][BMP];
    __shared__ float Bs[2][BK][BNP];
    __shared__ unsigned long long sred[BM];

    const int tid = threadIdx.x;
    const int tx = tid & 15;       // 0..15 -> N direction
    const int ty = tid >> 4;       // 0..15 -> M direction
    const int m0 = blockIdx.y * BM;
    const int n0 = blockIdx.x * BN;

    const int lr = tid >> 2;         // 0..63 : row within tile (and +64)
    const int lc = (tid & 3) << 2;   // 0,4,8,12 : k-offset of float4

    const float* Ap = A + (size_t)(m0 + lr) * K + lc;
    const float* Bp = B + (size_t)(n0 + lr) * K + lc;
    const size_t row64 = (size_t)64 * K;

    float acc[8][8];
    #pragma unroll
    for (int i = 0; i < 8; i++)
        #pragma unroll
        for (int j = 0; j < 8; j++) acc[i][j] = 0.f;

    // preload tile 0
    float4 a0 = *(const float4*)(Ap);
    float4 a1 = *(const float4*)(Ap + row64);
    float4 b0 = *(const float4*)(Bp);
    float4 b1 = *(const float4*)(Bp + row64);

    As[0][lc+0][lr]    = a0.x; As[0][lc+1][lr]    = a0.y; As[0][lc+2][lr]    = a0.z; As[0][lc+3][lr]    = a0.w;
    As[0][lc+0][lr+64] = a1.x; As[0][lc+1][lr+64] = a1.y; As[0][lc+2][lr+64] = a1.z; As[0][lc+3][lr+64] = a1.w;
    Bs[0][lc+0][lr]    = b0.x; Bs[0][lc+1][lr]    = b0.y; Bs[0][lc+2][lr]    = b0.z; Bs[0][lc+3][lr]    = b0.w;
    Bs[0][lc+0][lr+64] = b1.x; Bs[0][lc+1][lr+64] = b1.y; Bs[0][lc+2][lr+64] = b1.z; Bs[0][lc+3][lr+64] = b1.w;
    __syncthreads();

    const int nTiles = K / BK;
    int buf = 0;

    for (int kt = 1; kt < nTiles; kt++) {
        const float* Ap2 = Ap + kt * BK;
        const float* Bp2 = Bp + kt * BK;
        a0 = *(const float4*)(Ap2);
        a1 = *(const float4*)(Ap2 + row64);
        b0 = *(const float4*)(Bp2);
        b1 = *(const float4*)(Bp2 + row64);

        #pragma unroll
        for (int k = 0; k < BK; k++) {
            float a_frag[8], b_frag[8];
            *(float4*)&a_frag[0] = *(const float4*)&As[buf][k][ty * 8];
            *(float4*)&a_frag[4] = *(const float4*)&As[buf][k][ty * 8 + 4];
            *(float4*)&b_frag[0] = *(const float4*)&Bs[buf][k][tx * 8];
            *(float4*)&b_frag[4] = *(const float4*)&Bs[buf][k][tx * 8 + 4];
            #pragma unroll
            for (int i = 0; i < 8; i++)
                #pragma unroll
                for (int j = 0; j < 8; j++)
                    acc[i][j] = fmaf(a_frag[i], b_frag[j], acc[i][j]);
        }

        int nb = buf ^ 1;
        As[nb][lc+0][lr]    = a0.x; As[nb][lc+1][lr]    = a0.y; As[nb][lc+2][lr]    = a0.z; As[nb][lc+3][lr]    = a0.w;
        As[nb][lc+0][lr+64] = a1.x; As[nb][lc+1][lr+64] = a1.y; As[nb][lc+2][lr+64] = a1.z; As[nb][lc+3][lr+64] = a1.w;
        Bs[nb][lc+0][lr]    = b0.x; Bs[nb][lc+1][lr]    = b0.y; Bs[nb][lc+2][lr]    = b0.z; Bs[nb][lc+3][lr]    = b0.w;
        Bs[nb][lc+0][lr+64] = b1.x; Bs[nb][lc+1][lr+64] = b1.y; Bs[nb][lc+2][lr+64] = b1.z; Bs[nb][lc+3][lr+64] = b1.w;
        __syncthreads();
        buf = nb;
    }

    // last tile compute
    #pragma unroll
    for (int k = 0; k < BK; k++) {
        float a_frag[8], b_frag[8];
        *(float4*)&a_frag[0] = *(const float4*)&As[buf][k][ty * 8];
        *(float4*)&a_frag[4] = *(const float4*)&As[buf][k][ty * 8 + 4];
        *(float4*)&b_frag[0] = *(const float4*)&Bs[buf][k][tx * 8];
        *(float4*)&b_frag[4] = *(const float4*)&Bs[buf][k][tx * 8 + 4];
        #pragma unroll
        for (int i = 0; i < 8; i++)
            #pragma unroll
            for (int j = 0; j < 8; j++)
                acc[i][j] = fmaf(a_frag[i], b_frag[j], acc[i][j]);
    }

    // epilogue: dist = (zsq + esq) - 2*acc ; fused argmin
    float ze[8], ee[8];
    #pragma unroll
    for (int i = 0; i < 8; i++) ze[i] = g_zsq[m0 + ty * 8 + i];
    #pragma unroll
    for (int j = 0; j < 8; j++) ee[j] = g_esq[n0 + tx * 8 + j];

    if (tid < BM) sred[tid] = 0xFFFFFFFFFFFFFFFFull;
    __syncthreads();

    #pragma unroll
    for (int i = 0; i < 8; i++) {
        unsigned long long bk = 0xFFFFFFFFFFFFFFFFull;
        #pragma unroll
        for (int j = 0; j < 8; j++) {
            float t = ze[i] + ee[j];
            float d = t - 2.0f * acc[i][j];
            unsigned int u = __float_as_uint(d);
            u = (u & 0x80000000u) ? ~u : (u | 0x80000000u);  // total-order encode
            unsigned long long key =
                ((unsigned long long)u << 32) | (unsigned int)(n0 + tx * 8 + j);
            if (key < bk) bk = key;   // ascending j -> ties keep lowest index
        }
        atomicMin(&sred[ty * 8 + i], bk);
    }
    __syncthreads();
    if (tid < BM) atomicMin(&g_best[m0 + tid], sred[tid]);
}

// ---------------------------------------------------------------- gather + loss partials
__global__ void gather_loss_kernel(const float* __restrict__ z,
                                   const float* __restrict__ cb,
                                   float* __restrict__ out_q,
                                   float* __restrict__ out_idx,
                                   int K)
{
    int m = blockIdx.x;
    unsigned int idx = (unsigned int)(g_best[m] & 0xFFFFFFFFu);
    const float* zr = z + (size_t)m * K;
    const float* cr = cb + (size_t)idx * K;
    float s = 0.f;
    for (int c = threadIdx.x; c < K; c += 128) {
        float zev = zr[c];
        float zqv = cr[c];
        float dlt = zqv - zev;                 // straight-through: same rounding as ref
        out_q[(size_t)m * K + c] = zev + dlt;
        s += dlt * dlt;
    }
    #pragma unroll
    for (int o = 16; o; o >>= 1) s += __shfl_down_sync(0xffffffffu, s, o);
    __shared__ float ws[4];
    if ((threadIdx.x & 31) == 0) ws[threadIdx.x >> 5] = s;
    __syncthreads();
    if (threadIdx.x == 0) {
        g_partials[m] = ws[0] + ws[1] + ws[2] + ws[3];
        out_idx[m] = (float)idx;
    }
}

// ---------------------------------------------------------------- final loss
__global__ void loss_kernel(float* __restrict__ out_loss, int M, int K)
{
    __shared__ float sm[1024];
    float s = 0.f;
    for (int i = threadIdx.x; i < M; i += 1024) s += g_partials[i];
    sm[threadIdx.x] = s;
    __syncthreads();
    for (int o = 512; o; o >>= 1) {
        if (threadIdx.x < o) sm[threadIdx.x] += sm[threadIdx.x + o];
        __syncthreads();
    }
    if (threadIdx.x == 0) {
        float mean = sm[0] / ((float)M * (float)K);
        out_loss[0] = (mean + 0.25f * mean) / (float)K;   // (cb_loss + beta*commit)/C
    }
}

// ---------------------------------------------------------------- launch
extern "C" void kernel_launch(void* const* d_in, const int* in_sizes, int n_in,
                              void* d_out, int out_size)
{
    const float* z  = (const float*)d_in[0];   // [M, K]
    const float* cb = (const float*)d_in[1];   // [N, K]
    const int K = KDIM;
    const int M = in_sizes[0] / K;             // 32768
    const int N = in_sizes[1] / K;             // 8192

    float* out      = (float*)d_out;
    float* out_q    = out;                       // M*K
    float* out_idx  = out + (size_t)M * K;       // M
    float* out_loss = out_idx + M;               // 1

    rowsq_kernel<<<M, 128>>>(z, K, 0);
    rowsq_kernel<<<N, 128>>>(cb, K, 1);
    init_best_kernel<<<(M + 255) / 256, 256>>>(M);

    dim3 grid(N / BN, M / BM);
    gemm_argmin_kernel<<<grid, 256>>>(z, cb, K);

    gather_loss_kernel<<<M, 128>>>(z, cb, out_q, out_idx, K);
    loss_kernel<<<1, 1024>>>(out_loss, M, K);
}

// round 4
// speedup vs baseline: 2.0518x; 2.0518x over previous
#include <cuda_runtime.h>
#include <cuda_bf16.h>
#include <stdint.h>

// ----------------------------------------------------------------------------
// VQExpert via legacy tensor path (mma.sync bf16, base ISA -> compiles for
// compute_103). bf16x3 split folded into ONE GEMM with K'=1536:
//   A'' = [Ah | Ah | Al],  B'' = [Bh | Bl | Bh]  =>  A''.B'' = AhBh+AhBl+AlBh
// dist = (zsq + esq) - 2*dot, fused per-row argmin, then gather + loss.
// ----------------------------------------------------------------------------

#define KDIM 512
#define K3   1536
#define MDIM 32768
#define NDIM 8192
#define BM 128
#define BN 128
#define BK 64
#define STAGES 3
#define STAGE_BYTES (2 * BM * BK)       // 16384 (A tile); B tile same size
#define STAGE_TOTAL (2 * STAGE_BYTES)   // 32768
#define NKT (K3 / BK)                   // 24

__device__ __align__(16) __nv_bfloat16 g_A3[(size_t)MDIM * K3];
__device__ __align__(16) __nv_bfloat16 g_B3[(size_t)NDIM * K3];
__device__ float g_zsq[MDIM];
__device__ float g_esq[NDIM];
__device__ unsigned long long g_best[MDIM];
__device__ float g_partials[MDIM];

// ------------------------------------------------------------ PTX helpers
__device__ __forceinline__ uint32_t smem_u32(const void* p) {
    uint32_t a;
    asm("{ .reg .u64 t; cvta.to.shared.u64 t, %1; cvt.u32.u64 %0, t; }"
        : "=r"(a) : "l"(p));
    return a;
}
__device__ __forceinline__ void cp16(uint32_t dst, const void* src) {
    asm volatile("cp.async.cg.shared.global [%0], [%1], 16;"
                 :: "r"(dst), "l"(src) : "memory");
}
__device__ __forceinline__ void ldsm4(uint32_t* r, uint32_t addr) {
    asm volatile("ldmatrix.sync.aligned.m8n8.x4.shared.b16 {%0,%1,%2,%3}, [%4];"
                 : "=r"(r[0]), "=r"(r[1]), "=r"(r[2]), "=r"(r[3]) : "r"(addr));
}
__device__ __forceinline__ void mma16816(float* c, const uint32_t* a,
                                         uint32_t b0, uint32_t b1) {
    asm volatile(
        "mma.sync.aligned.m16n8k16.row.col.f32.bf16.bf16.f32 "
        "{%0,%1,%2,%3}, {%4,%5,%6,%7}, {%8,%9}, {%0,%1,%2,%3};"
        : "+f"(c[0]), "+f"(c[1]), "+f"(c[2]), "+f"(c[3])
        : "r"(a[0]), "r"(a[1]), "r"(a[2]), "r"(a[3]), "r"(b0), "r"(b1));
}
__device__ __forceinline__ uint32_t swz(uint32_t off) {
    return off ^ ((off >> 3) & 0x70);
}
__device__ __forceinline__ uint32_t packbf2(__nv_bfloat16 a, __nv_bfloat16 b) {
    __nv_bfloat162 t; t.x = a; t.y = b;
    return *(uint32_t*)&t;
}

// ------------------------------------------------------------ split kernels
__global__ void splitA_kernel(const float* __restrict__ z)
{
    int i = blockIdx.x * 256 + threadIdx.x;     // over MDIM*128
    int m = i >> 7, kc = (i & 127) << 2;
    float4 v = *(const float4*)(z + (size_t)m * KDIM + kc);
    __nv_bfloat16 h0 = __float2bfloat16(v.x), h1 = __float2bfloat16(v.y);
    __nv_bfloat16 h2 = __float2bfloat16(v.z), h3 = __float2bfloat16(v.w);
    __nv_bfloat16 l0 = __float2bfloat16(v.x - __bfloat162float(h0));
    __nv_bfloat16 l1 = __float2bfloat16(v.y - __bfloat162float(h1));
    __nv_bfloat16 l2 = __float2bfloat16(v.z - __bfloat162float(h2));
    __nv_bfloat16 l3 = __float2bfloat16(v.w - __bfloat162float(h3));
    uint2 H; H.x = packbf2(h0, h1); H.y = packbf2(h2, h3);
    uint2 L; L.x = packbf2(l0, l1); L.y = packbf2(l2, l3);
    __nv_bfloat16* row = g_A3 + (size_t)m * K3 + kc;
    *(uint2*)(row)        = H;   // Ah
    *(uint2*)(row + 512)  = H;   // Ah again
    *(uint2*)(row + 1024) = L;   // Al
}
__global__ void splitB_kernel(const float* __restrict__ cb)
{
    int i = blockIdx.x * 256 + threadIdx.x;     // over NDIM*128
    int n = i >> 7, kc = (i & 127) << 2;
    float4 v = *(const float4*)(cb + (size_t)n * KDIM + kc);
    __nv_bfloat16 h0 = __float2bfloat16(v.x), h1 = __float2bfloat16(v.y);
    __nv_bfloat16 h2 = __float2bfloat16(v.z), h3 = __float2bfloat16(v.w);
    __nv_bfloat16 l0 = __float2bfloat16(v.x - __bfloat162float(h0));
    __nv_bfloat16 l1 = __float2bfloat16(v.y - __bfloat162float(h1));
    __nv_bfloat16 l2 = __float2bfloat16(v.z - __bfloat162float(h2));
    __nv_bfloat16 l3 = __float2bfloat16(v.w - __bfloat162float(h3));
    uint2 H; H.x = packbf2(h0, h1); H.y = packbf2(h2, h3);
    uint2 L; L.x = packbf2(l0, l1); L.y = packbf2(l2, l3);
    __nv_bfloat16* row = g_B3 + (size_t)n * K3 + kc;
    *(uint2*)(row)        = H;   // Bh
    *(uint2*)(row + 512)  = L;   // Bl
    *(uint2*)(row + 1024) = H;   // Bh again
}

// ------------------------------------------------------------ row sumsq
__global__ void rowsq_kernel(const float* __restrict__ x, int K, int which)
{
    int row = blockIdx.x;
    const float* xr = x + (size_t)row * K;
    float s = 0.f;
    for (int c = threadIdx.x; c < K; c += 128) { float v = xr[c]; s += v * v; }
    #pragma unroll
    for (int o = 16; o; o >>= 1) s += __shfl_down_sync(0xffffffffu, s, o);
    __shared__ float ws[4];
    if ((threadIdx.x & 31) == 0) ws[threadIdx.x >> 5] = s;
    __syncthreads();
    if (threadIdx.x == 0) {
        float t = ws[0] + ws[1] + ws[2] + ws[3];
        if (which) g_esq[row] = t; else g_zsq[row] = t;
    }
}

__global__ void init_best_kernel(int M)
{
    int i = blockIdx.x * blockDim.x + threadIdx.x;
    if (i < M) g_best[i] = 0xFFFFFFFFFFFFFFFFull;
}

// ------------------------------------------------------------ HMMA GEMM+argmin
__global__ __launch_bounds__(256, 1)
void gemm_hmma_kernel()
{
    extern __shared__ char smem[];
    __shared__ unsigned long long sred[BM];
    __shared__ float s_esq[BN];
    const uint32_t smb = smem_u32(smem);
    const int tid = threadIdx.x;
    const int m0 = blockIdx.y * BM;
    const int n0 = blockIdx.x * BN;

    // per-thread cp.async chunk descriptors (4 A-chunks + 4 B-chunks / stage)
    uint32_t dstA[4], dstB[4];
    const __nv_bfloat16 *srcA[4], *srcB[4];
    #pragma unroll
    for (int r = 0; r < 4; r++) {
        int c = tid + r * 256, row = c >> 3, c16 = c & 7;
        uint32_t sw = swz(row * 128 + c16 * 16);
        dstA[r] = smb + sw;
        dstB[r] = smb + STAGE_BYTES + sw;
        srcA[r] = g_A3 + (size_t)(m0 + row) * K3 + c16 * 8;
        srcB[r] = g_B3 + (size_t)(n0 + row) * K3 + c16 * 8;
    }

    // prologue: stages 0..STAGES-2
    #pragma unroll
    for (int s = 0; s < STAGES - 1; s++) {
        uint32_t so = s * STAGE_TOTAL;
        #pragma unroll
        for (int r = 0; r < 4; r++) {
            cp16(dstA[r] + so, srcA[r] + s * BK);
            cp16(dstB[r] + so, srcB[r] + s * BK);
        }
        asm volatile("cp.async.commit_group;" ::: "memory");
    }

    if (tid < BM) sred[tid] = 0xFFFFFFFFFFFFFFFFull;
    if (tid < BN) s_esq[tid] = g_esq[n0 + tid];

    float acc[4][4][4];
    #pragma unroll
    for (int i = 0; i < 4; i++)
        #pragma unroll
        for (int j = 0; j < 4; j++)
            #pragma unroll
            for (int q = 0; q < 4; q++) acc[i][j][q] = 0.f;

    const int lane = tid & 31, warp = tid >> 5;
    const int wm = (warp & 1) * 64;       // warp row base (2 warps in M)
    const int wn = (warp >> 1) * 32;      // warp col base (4 warps in N)
    const uint32_t a_row = wm + (lane & 15);
    const uint32_t b_row = wn + (lane & 15);
    const uint32_t kchunk = (lane >> 4);  // 0/1: which 16B chunk of the k16 slice

    for (int kt = 0; kt < NKT; kt++) {
        asm volatile("cp.async.wait_group %0;" :: "n"(STAGES - 2));
        __syncthreads();

        // prefetch stage kt+STAGES-1 (overwrites buffer compute just released)
        int pf = kt + STAGES - 1;
        if (pf < NKT) {
            uint32_t so = (uint32_t)(pf % STAGES) * STAGE_TOTAL;
            #pragma unroll
            for (int r = 0; r < 4; r++) {
                cp16(dstA[r] + so, srcA[r] + pf * BK);
                cp16(dstB[r] + so, srcB[r] + pf * BK);
            }
        }
        asm volatile("cp.async.commit_group;" ::: "memory");

        const uint32_t sA = smb + (uint32_t)(kt % STAGES) * STAGE_TOTAL;
        const uint32_t sB = sA + STAGE_BYTES;
        #pragma unroll
        for (int kk = 0; kk < 4; kk++) {
            uint32_t a[4][4], b[2][4];
            #pragma unroll
            for (int i = 0; i < 4; i++) {
                uint32_t off = (a_row + i * 16) * 128 + (kk * 2 + kchunk) * 16;
                ldsm4(a[i], sA + swz(off));
            }
            #pragma unroll
            for (int p = 0; p < 2; p++) {
                uint32_t off = (b_row + p * 16) * 128 + (kk * 2 + kchunk) * 16;
                ldsm4(b[p], sB + swz(off));
            }
            #pragma unroll
            for (int i = 0; i < 4; i++)
                #pragma unroll
                for (int j = 0; j < 4; j++) {
                    int p = j >> 1, h = j & 1;
                    mma16816(acc[i][j], a[i], b[p][h], b[p][h + 2]);
                }
        }
    }

    // ---- epilogue: dist = (zsq+esq) - 2*acc, fused per-row argmin
    const int r0 = lane >> 2;
    #pragma unroll
    for (int i = 0; i < 4; i++) {
        int rowa = wm + i * 16 + r0;
        float zs0 = g_zsq[m0 + rowa];
        float zs1 = g_zsq[m0 + rowa + 8];
        unsigned long long bk0 = 0xFFFFFFFFFFFFFFFFull;
        unsigned long long bk1 = 0xFFFFFFFFFFFFFFFFull;
        #pragma unroll
        for (int j = 0; j < 4; j++) {
            int ncol = wn + j * 8 + 2 * (lane & 3);
            float e0 = s_esq[ncol], e1 = s_esq[ncol + 1];
            unsigned gn0 = (unsigned)(n0 + ncol), gn1 = gn0 + 1;
            float d;
            unsigned u;
            unsigned long long k;
            d = (zs0 + e0) - 2.0f * acc[i][j][0];
            u = __float_as_uint(d); u = (u & 0x80000000u) ? ~u : (u | 0x80000000u);
            k = ((unsigned long long)u << 32) | gn0; if (k < bk0) bk0 = k;
            d = (zs0 + e1) - 2.0f * acc[i][j][1];
            u = __float_as_uint(d); u = (u & 0x80000000u) ? ~u : (u | 0x80000000u);
            k = ((unsigned long long)u << 32) | gn1; if (k < bk0) bk0 = k;
            d = (zs1 + e0) - 2.0f * acc[i][j][2];
            u = __float_as_uint(d); u = (u & 0x80000000u) ? ~u : (u | 0x80000000u);
            k = ((unsigned long long)u << 32) | gn0; if (k < bk1) bk1 = k;
            d = (zs1 + e1) - 2.0f * acc[i][j][3];
            u = __float_as_uint(d); u = (u & 0x80000000u) ? ~u : (u | 0x80000000u);
            k = ((unsigned long long)u << 32) | gn1; if (k < bk1) bk1 = k;
        }
        // reduce across the 4 lanes sharing this row
        #pragma unroll
        for (int o = 1; o <= 2; o <<= 1) {
            unsigned long long t0 = __shfl_xor_sync(0xffffffffu, bk0, o);
            unsigned long long t1 = __shfl_xor_sync(0xffffffffu, bk1, o);
            if (t0 < bk0) bk0 = t0;
            if (t1 < bk1) bk1 = t1;
        }
        if ((lane & 3) == 0) {
            atomicMin(&sred[rowa], bk0);
            atomicMin(&sred[rowa + 8], bk1);
        }
    }
    __syncthreads();
    if (tid < BM) atomicMin(&g_best[m0 + tid], sred[tid]);
}

// ------------------------------------------------------------ gather + loss
__global__ void gather_loss_kernel(const float* __restrict__ z,
                                   const float* __restrict__ cb,
                                   float* __restrict__ out_q,
                                   float* __restrict__ out_idx)
{
    int m = blockIdx.x;
    unsigned int idx = (unsigned int)(g_best[m] & 0xFFFFFFFFu);
    const float4* zr = (const float4*)(z + (size_t)m * KDIM);
    const float4* cr = (const float4*)(cb + (size_t)idx * KDIM);
    float4* qr = (float4*)(out_q + (size_t)m * KDIM);
    float4 ze = zr[threadIdx.x];
    float4 cq = cr[threadIdx.x];
    float d0 = cq.x - ze.x, d1 = cq.y - ze.y, d2 = cq.z - ze.z, d3 = cq.w - ze.w;
    float4 o;
    o.x = ze.x + d0; o.y = ze.y + d1; o.z = ze.z + d2; o.w = ze.w + d3;
    qr[threadIdx.x] = o;
    float s = d0 * d0 + d1 * d1 + d2 * d2 + d3 * d3;
    #pragma unroll
    for (int off = 16; off; off >>= 1) s += __shfl_down_sync(0xffffffffu, s, off);
    __shared__ float ws[4];
    if ((threadIdx.x & 31) == 0) ws[threadIdx.x >> 5] = s;
    __syncthreads();
    if (threadIdx.x == 0) {
        g_partials[m] = ws[0] + ws[1] + ws[2] + ws[3];
        out_idx[m] = (float)idx;
    }
}

__global__ void loss_kernel(float* __restrict__ out_loss, int M, int K)
{
    __shared__ float sm[1024];
    float s = 0.f;
    for (int i = threadIdx.x; i < M; i += 1024) s += g_partials[i];
    sm[threadIdx.x] = s;
    __syncthreads();
    for (int o = 512; o; o >>= 1) {
        if (threadIdx.x < o) sm[threadIdx.x] += sm[threadIdx.x + o];
        __syncthreads();
    }
    if (threadIdx.x == 0) {
        float mean = sm[0] / ((float)M * (float)K);
        out_loss[0] = (mean + 0.25f * mean) / (float)K;
    }
}

// ------------------------------------------------------------ launch
extern "C" void kernel_launch(void* const* d_in, const int* in_sizes, int n_in,
                              void* d_out, int out_size)
{
    const float* z  = (const float*)d_in[0];
    const float* cb = (const float*)d_in[1];
    const int M = in_sizes[0] / KDIM;   // 32768
    const int N = in_sizes[1] / KDIM;   // 8192

    float* out      = (float*)d_out;
    float* out_q    = out;
    float* out_idx  = out + (size_t)M * KDIM;
    float* out_loss = out_idx + M;

    static int attr_done = 0;
    if (!attr_done) {
        cudaFuncSetAttribute(gemm_hmma_kernel,
                             cudaFuncAttributeMaxDynamicSharedMemorySize,
                             STAGES * STAGE_TOTAL);
        attr_done = 1;
    }

    splitA_kernel<<<M * 128 / 256, 256>>>(z);
    splitB_kernel<<<N * 128 / 256, 256>>>(cb);
    rowsq_kernel<<<M, 128>>>(z, KDIM, 0);
    rowsq_kernel<<<N, 128>>>(cb, KDIM, 1);
    init_best_kernel<<<(M + 255) / 256, 256>>>(M);

    dim3 grid(N / BN, M / BM);
    gemm_hmma_kernel<<<grid, 256, STAGES * STAGE_TOTAL>>>();

    gather_loss_kernel<<<M, 128>>>(z, cb, out_q, out_idx);
    loss_kernel<<<1, 1024>>>(out_loss, M, KDIM);
}

// round 6
// speedup vs baseline: 2.2006x; 1.0725x over previous
#include <cuda_runtime.h>
#include <cuda_bf16.h>
#include <stdint.h>

// ----------------------------------------------------------------------------
// VQExpert via mma.sync bf16 (base ISA -> compiles for compute_103).
// bf16x3 split with shared-operand tiles: per k-tile load Ah,Al,Bh,Bl once,
// accumulate dot = Ah*Bh + Al*Bh + Ah*Bl (fp32 accum; AlBl dropped ~2e-6).
// dist = (zsq + esq) - 2*dot, fused per-row argmin, then gather + loss.
// GEMM core (fragments, pipeline, epilogue) is verbatim from the passing R4.
// ----------------------------------------------------------------------------

#define KDIM 512
#define MDIM 32768
#define NDIM 8192
#define BM 128
#define BN 128
#define BK 64
#define STAGES 3
#define NKT (KDIM / BK)        // 8
// stage regions: Ah @0 | Al @16K | Bh @32K | Bl @48K ; stage = 64KB
#define R_AL 16384
#define R_BH 32768
#define R_BL 49152
#define STG  65536
#define SMEM_DYN (STAGES * STG)   // 196608

__device__ __align__(16) __nv_bfloat16 g_Ah[(size_t)MDIM * KDIM];
__device__ __align__(16) __nv_bfloat16 g_Al[(size_t)MDIM * KDIM];
__device__ __align__(16) __nv_bfloat16 g_Bh[(size_t)NDIM * KDIM];
__device__ __align__(16) __nv_bfloat16 g_Bl[(size_t)NDIM * KDIM];
__device__ float g_zsq[MDIM];
__device__ float g_esq[NDIM];
__device__ unsigned long long g_best[MDIM];
__device__ float g_partials[MDIM];

// ------------------------------------------------------------ PTX helpers
__device__ __forceinline__ uint32_t smem_u32(const void* p) {
    uint32_t a;
    asm("{ .reg .u64 t; cvta.to.shared.u64 t, %1; cvt.u32.u64 %0, t; }"
        : "=r"(a) : "l"(p));
    return a;
}
__device__ __forceinline__ void cp16(uint32_t dst, const void* src) {
    asm volatile("cp.async.cg.shared.global [%0], [%1], 16;"
                 :: "r"(dst), "l"(src) : "memory");
}
__device__ __forceinline__ void ldsm4(uint32_t* r, uint32_t addr) {
    asm volatile("ldmatrix.sync.aligned.m8n8.x4.shared.b16 {%0,%1,%2,%3}, [%4];"
                 : "=r"(r[0]), "=r"(r[1]), "=r"(r[2]), "=r"(r[3]) : "r"(addr));
}
__device__ __forceinline__ void mma16816(float* c, const uint32_t* a,
                                         uint32_t b0, uint32_t b1) {
    asm volatile(
        "mma.sync.aligned.m16n8k16.row.col.f32.bf16.bf16.f32 "
        "{%0,%1,%2,%3}, {%4,%5,%6,%7}, {%8,%9}, {%0,%1,%2,%3};"
        : "+f"(c[0]), "+f"(c[1]), "+f"(c[2]), "+f"(c[3])
        : "r"(a[0]), "r"(a[1]), "r"(a[2]), "r"(a[3]), "r"(b0), "r"(b1));
}
__device__ __forceinline__ uint32_t swz(uint32_t off) {
    return off ^ ((off >> 3) & 0x70);
}
__device__ __forceinline__ uint32_t packbf2(__nv_bfloat16 a, __nv_bfloat16 b) {
    __nv_bfloat162 t; t.x = a; t.y = b;
    return *(uint32_t*)&t;
}

// ------------------------------------------------------------ split kernels
__global__ void splitA_kernel(const float* __restrict__ z)
{
    int i = blockIdx.x * 256 + threadIdx.x;     // over MDIM*128
    int m = i >> 7, kc = (i & 127) << 2;
    float4 v = *(const float4*)(z + (size_t)m * KDIM + kc);
    __nv_bfloat16 h0 = __float2bfloat16(v.x), h1 = __float2bfloat16(v.y);
    __nv_bfloat16 h2 = __float2bfloat16(v.z), h3 = __float2bfloat16(v.w);
    __nv_bfloat16 l0 = __float2bfloat16(v.x - __bfloat162float(h0));
    __nv_bfloat16 l1 = __float2bfloat16(v.y - __bfloat162float(h1));
    __nv_bfloat16 l2 = __float2bfloat16(v.z - __bfloat162float(h2));
    __nv_bfloat16 l3 = __float2bfloat16(v.w - __bfloat162float(h3));
    uint2 H; H.x = packbf2(h0, h1); H.y = packbf2(h2, h3);
    uint2 L; L.x = packbf2(l0, l1); L.y = packbf2(l2, l3);
    *(uint2*)(g_Ah + (size_t)m * KDIM + kc) = H;
    *(uint2*)(g_Al + (size_t)m * KDIM + kc) = L;
}
__global__ void splitB_kernel(const float* __restrict__ cb)
{
    int i = blockIdx.x * 256 + threadIdx.x;     // over NDIM*128
    int n = i >> 7, kc = (i & 127) << 2;
    float4 v = *(const float4*)(cb + (size_t)n * KDIM + kc);
    __nv_bfloat16 h0 = __float2bfloat16(v.x), h1 = __float2bfloat16(v.y);
    __nv_bfloat16 h2 = __float2bfloat16(v.z), h3 = __float2bfloat16(v.w);
    __nv_bfloat16 l0 = __float2bfloat16(v.x - __bfloat162float(h0));
    __nv_bfloat16 l1 = __float2bfloat16(v.y - __bfloat162float(h1));
    __nv_bfloat16 l2 = __float2bfloat16(v.z - __bfloat162float(h2));
    __nv_bfloat16 l3 = __float2bfloat16(v.w - __bfloat162float(h3));
    uint2 H; H.x = packbf2(h0, h1); H.y = packbf2(h2, h3);
    uint2 L; L.x = packbf2(l0, l1); L.y = packbf2(l2, l3);
    *(uint2*)(g_Bh + (size_t)n * KDIM + kc) = H;
    *(uint2*)(g_Bl + (size_t)n * KDIM + kc) = L;
}

// ------------------------------------------------------------ row sumsq
__global__ void rowsq_kernel(const float* __restrict__ x, int K, int which)
{
    int row = blockIdx.x;
    const float* xr = x + (size_t)row * K;
    float s = 0.f;
    for (int c = threadIdx.x; c < K; c += 128) { float v = xr[c]; s += v * v; }
    #pragma unroll
    for (int o = 16; o; o >>= 1) s += __shfl_down_sync(0xffffffffu, s, o);
    __shared__ float ws[4];
    if ((threadIdx.x & 31) == 0) ws[threadIdx.x >> 5] = s;
    __syncthreads();
    if (threadIdx.x == 0) {
        float t = ws[0] + ws[1] + ws[2] + ws[3];
        if (which) g_esq[row] = t; else g_zsq[row] = t;
    }
}

__global__ void init_best_kernel(int M)
{
    int i = blockIdx.x * blockDim.x + threadIdx.x;
    if (i < M) g_best[i] = 0xFFFFFFFFFFFFFFFFull;
}

// ------------------------------------------------------------ HMMA GEMM+argmin
__global__ __launch_bounds__(256, 1)
void gemm_hmma_kernel()
{
    extern __shared__ char smem[];
    __shared__ unsigned long long sred[BM];
    __shared__ float s_esq[BN];
    const uint32_t smb = smem_u32(smem);
    const int tid = threadIdx.x;
    const int lane = tid & 31, warp = tid >> 5;
    const int m0 = blockIdx.y * BM;
    const int n0 = blockIdx.x * BN;

    // per-thread cp.async chunk descriptors: each 16KB region = 4 chunks/thread
    uint32_t swo[4];
    const __nv_bfloat16 *sAh[4], *sAl[4], *sBh[4], *sBl[4];
    #pragma unroll
    for (int r = 0; r < 4; r++) {
        int q = tid + r * 256, row = q >> 3, c = q & 7;
        swo[r] = swz(row * 128 + c * 16);
        sAh[r] = g_Ah + (size_t)(m0 + row) * KDIM + c * 8;
        sAl[r] = g_Al + (size_t)(m0 + row) * KDIM + c * 8;
        sBh[r] = g_Bh + (size_t)(n0 + row) * KDIM + c * 8;
        sBl[r] = g_Bl + (size_t)(n0 + row) * KDIM + c * 8;
    }

    // prologue: stages 0..STAGES-2
    #pragma unroll
    for (int s = 0; s < STAGES - 1; s++) {
        uint32_t bo = (uint32_t)s * STG;
        int k0 = s * BK;
        #pragma unroll
        for (int r = 0; r < 4; r++) {
            cp16(smb + bo + swo[r],        sAh[r] + k0);
            cp16(smb + bo + R_AL + swo[r], sAl[r] + k0);
            cp16(smb + bo + R_BH + swo[r], sBh[r] + k0);
            cp16(smb + bo + R_BL + swo[r], sBl[r] + k0);
        }
        asm volatile("cp.async.commit_group;" ::: "memory");
    }

    if (tid < BM) sred[tid] = 0xFFFFFFFFFFFFFFFFull;
    if (tid < BN) s_esq[tid] = g_esq[n0 + tid];

    float acc[4][4][4];
    #pragma unroll
    for (int i = 0; i < 4; i++)
        #pragma unroll
        for (int j = 0; j < 4; j++)
            #pragma unroll
            for (int q = 0; q < 4; q++) acc[i][j][q] = 0.f;

    const int wm = (warp & 1) * 64;       // warp row base (2 warps in M)
    const int wn = (warp >> 1) * 32;      // warp col base (4 warps in N)
    const uint32_t a_row = wm + (lane & 15);
    const uint32_t b_row = wn + (lane & 15);
    const uint32_t kchunk = (lane >> 4);  // 0/1: which 16B chunk of the k16 slice

    for (int kt = 0; kt < NKT; kt++) {
        asm volatile("cp.async.wait_group %0;" :: "n"(STAGES - 2));
        __syncthreads();

        // prefetch stage kt+STAGES-1 (overwrites buffer compute just released)
        int pf = kt + STAGES - 1;
        if (pf < NKT) {
            uint32_t bo = (uint32_t)(pf % STAGES) * STG;
            int k0 = pf * BK;
            #pragma unroll
            for (int r = 0; r < 4; r++) {
                cp16(smb + bo + swo[r],        sAh[r] + k0);
                cp16(smb + bo + R_AL + swo[r], sAl[r] + k0);
                cp16(smb + bo + R_BH + swo[r], sBh[r] + k0);
                cp16(smb + bo + R_BL + swo[r], sBl[r] + k0);
            }
        }
        asm volatile("cp.async.commit_group;" ::: "memory");

        const uint32_t sA = smb + (uint32_t)(kt % STAGES) * STG;
        #pragma unroll
        for (int kk = 0; kk < 4; kk++) {
            const uint32_t kof = (kk * 2 + kchunk) * 16;
            uint32_t aH[4][4], aL[4][4], b[2][4];
            #pragma unroll
            for (int i = 0; i < 4; i++)
                ldsm4(aH[i], sA + swz((a_row + i * 16) * 128 + kof));
            #pragma unroll
            for (int i = 0; i < 4; i++)
                ldsm4(aL[i], sA + R_AL + swz((a_row + i * 16) * 128 + kof));
            #pragma unroll
            for (int p = 0; p < 2; p++)
                ldsm4(b[p], sA + R_BH + swz((b_row + p * 16) * 128 + kof));
            #pragma unroll
            for (int i = 0; i < 4; i++)
                #pragma unroll
                for (int j = 0; j < 4; j++) {
                    int p = j >> 1, h = j & 1;
                    mma16816(acc[i][j], aH[i], b[p][h], b[p][h + 2]);
                }
            #pragma unroll
            for (int i = 0; i < 4; i++)
                #pragma unroll
                for (int j = 0; j < 4; j++) {
                    int p = j >> 1, h = j & 1;
                    mma16816(acc[i][j], aL[i], b[p][h], b[p][h + 2]);
                }
            #pragma unroll
            for (int p = 0; p < 2; p++)
                ldsm4(b[p], sA + R_BL + swz((b_row + p * 16) * 128 + kof));
            #pragma unroll
            for (int i = 0; i < 4; i++)
                #pragma unroll
                for (int j = 0; j < 4; j++) {
                    int p = j >> 1, h = j & 1;
                    mma16816(acc[i][j], aH[i], b[p][h], b[p][h + 2]);
                }
        }
    }

    // ---- epilogue: dist = (zsq+esq) - 2*acc, fused per-row argmin
    const int r0 = lane >> 2;
    #pragma unroll
    for (int i = 0; i < 4; i++) {
        int rowa = wm + i * 16 + r0;
        float zs0 = g_zsq[m0 + rowa];
        float zs1 = g_zsq[m0 + rowa + 8];
        unsigned long long bk0 = 0xFFFFFFFFFFFFFFFFull;
        unsigned long long bk1 = 0xFFFFFFFFFFFFFFFFull;
        #pragma unroll
        for (int j = 0; j < 4; j++) {
            int ncol = wn + j * 8 + 2 * (lane & 3);
            float e0 = s_esq[ncol], e1 = s_esq[ncol + 1];
            unsigned gn0 = (unsigned)(n0 + ncol), gn1 = gn0 + 1;
            float d;
            unsigned u;
            unsigned long long k;
            d = (zs0 + e0) - 2.0f * acc[i][j][0];
            u = __float_as_uint(d); u = (u & 0x80000000u) ? ~u : (u | 0x80000000u);
            k = ((unsigned long long)u << 32) | gn0; if (k < bk0) bk0 = k;
            d = (zs0 + e1) - 2.0f * acc[i][j][1];
            u = __float_as_uint(d); u = (u & 0x80000000u) ? ~u : (u | 0x80000000u);
            k = ((unsigned long long)u << 32) | gn1; if (k < bk0) bk0 = k;
            d = (zs1 + e0) - 2.0f * acc[i][j][2];
            u = __float_as_uint(d); u = (u & 0x80000000u) ? ~u : (u | 0x80000000u);
            k = ((unsigned long long)u << 32) | gn0; if (k < bk1) bk1 = k;
            d = (zs1 + e1) - 2.0f * acc[i][j][3];
            u = __float_as_uint(d); u = (u & 0x80000000u) ? ~u : (u | 0x80000000u);
            k = ((unsigned long long)u << 32) | gn1; if (k < bk1) bk1 = k;
        }
        // reduce across the 4 lanes sharing this row
        #pragma unroll
        for (int o = 1; o <= 2; o <<= 1) {
            unsigned long long t0 = __shfl_xor_sync(0xffffffffu, bk0, o);
            unsigned long long t1 = __shfl_xor_sync(0xffffffffu, bk1, o);
            if (t0 < bk0) bk0 = t0;
            if (t1 < bk1) bk1 = t1;
        }
        if ((lane & 3) == 0) {
            atomicMin(&sred[rowa], bk0);
            atomicMin(&sred[rowa + 8], bk1);
        }
    }
    __syncthreads();
    if (tid < BM) atomicMin(&g_best[m0 + tid], sred[tid]);
}

// ------------------------------------------------------------ gather + loss
__global__ void gather_loss_kernel(const float* __restrict__ z,
                                   const float* __restrict__ cb,
                                   float* __restrict__ out_q,
                                   float* __restrict__ out_idx)
{
    int m = blockIdx.x;
    unsigned int idx = (unsigned int)(g_best[m] & 0xFFFFFFFFu);
    const float4* zr = (const float4*)(z + (size_t)m * KDIM);
    const float4* cr = (const float4*)(cb + (size_t)idx * KDIM);
    float4* qr = (float4*)(out_q + (size_t)m * KDIM);
    float4 ze = zr[threadIdx.x];
    float4 cq = cr[threadIdx.x];
    float d0 = cq.x - ze.x, d1 = cq.y - ze.y, d2 = cq.z - ze.z, d3 = cq.w - ze.w;
    float4 o;
    o.x = ze.x + d0; o.y = ze.y + d1; o.z = ze.z + d2; o.w = ze.w + d3;
    qr[threadIdx.x] = o;
    float s = d0 * d0 + d1 * d1 + d2 * d2 + d3 * d3;
    #pragma unroll
    for (int off = 16; off; off >>= 1) s += __shfl_down_sync(0xffffffffu, s, off);
    __shared__ float ws[4];
    if ((threadIdx.x & 31) == 0) ws[threadIdx.x >> 5] = s;
    __syncthreads();
    if (threadIdx.x == 0) {
        g_partials[m] = ws[0] + ws[1] + ws[2] + ws[3];
        out_idx[m] = (float)idx;
    }
}

__global__ void loss_kernel(float* __restrict__ out_loss, int M, int K)
{
    __shared__ float sm[1024];
    float s = 0.f;
    for (int i = threadIdx.x; i < M; i += 1024) s += g_partials[i];
    sm[threadIdx.x] = s;
    __syncthreads();
    for (int o = 512; o; o >>= 1) {
        if (threadIdx.x < o) sm[threadIdx.x] += sm[threadIdx.x + o];
        __syncthreads();
    }
    if (threadIdx.x == 0) {
        float mean = sm[0] / ((float)M * (float)K);
        out_loss[0] = (mean + 0.25f * mean) / (float)K;
    }
}

// ------------------------------------------------------------ launch
extern "C" void kernel_launch(void* const* d_in, const int* in_sizes, int n_in,
                              void* d_out, int out_size)
{
    const float* z  = (const float*)d_in[0];
    const float* cb = (const float*)d_in[1];
    const int M = in_sizes[0] / KDIM;   // 32768
    const int N = in_sizes[1] / KDIM;   // 8192

    float* out      = (float*)d_out;
    float* out_q    = out;
    float* out_idx  = out + (size_t)M * KDIM;
    float* out_loss = out_idx + M;

    static int attr_done = 0;
    if (!attr_done) {
        cudaFuncSetAttribute(gemm_hmma_kernel,
                             cudaFuncAttributeMaxDynamicSharedMemorySize,
                             SMEM_DYN);
        attr_done = 1;
    }

    splitA_kernel<<<M * 128 / 256, 256>>>(z);
    splitB_kernel<<<N * 128 / 256, 256>>>(cb);
    rowsq_kernel<<<M, 128>>>(z, KDIM, 0);
    rowsq_kernel<<<N, 128>>>(cb, KDIM, 1);
    init_best_kernel<<<(M + 255) / 256, 256>>>(M);

    dim3 grid(N / BN, M / BM);
    gemm_hmma_kernel<<<grid, 256, SMEM_DYN>>>();

    gather_loss_kernel<<<M, 128>>>(z, cb, out_q, out_idx);
    loss_kernel<<<1, 1024>>>(out_loss, M, KDIM);
}

// round 7
// speedup vs baseline: 2.4587x; 1.1173x over previous
#include <cuda_runtime.h>
#include <cuda_bf16.h>
#include <stdint.h>

// ----------------------------------------------------------------------------
// VQExpert via mma.sync bf16 (base ISA -> compiles for compute_103).
// bf16x3 split with shared-operand tiles: per k-tile load Ah,Al,Bh,Bl once,
// accumulate dot = Ah*Bh + Al*Bh + Ah*Bl (fp32 accum; AlBl dropped ~2e-6).
// dist = (zsq + esq) - 2*dot, fused per-row argmin, then gather + loss.
// R7: BK=32 (SW64 rows), 96KB smem -> 2 CTAs/SM for latency hiding.
// ----------------------------------------------------------------------------

#define KDIM 512
#define MDIM 32768
#define NDIM 8192
#define BM 128
#define BN 128
#define BK 32
#define STAGES 3
#define NKT (KDIM / BK)        // 16
// stage regions (each BM*BK*2 = 8KB): Ah | Al | Bh | Bl ; stage = 32KB
#define R_AL 8192
#define R_BH 16384
#define R_BL 24576
#define STG  32768
#define SMEM_DYN (STAGES * STG)   // 98304

__device__ __align__(16) __nv_bfloat16 g_Ah[(size_t)MDIM * KDIM];
__device__ __align__(16) __nv_bfloat16 g_Al[(size_t)MDIM * KDIM];
__device__ __align__(16) __nv_bfloat16 g_Bh[(size_t)NDIM * KDIM];
__device__ __align__(16) __nv_bfloat16 g_Bl[(size_t)NDIM * KDIM];
__device__ float g_zsq[MDIM];
__device__ float g_esq[NDIM];
__device__ unsigned long long g_best[MDIM];
__device__ float g_partials[MDIM];

// ------------------------------------------------------------ PTX helpers
__device__ __forceinline__ uint32_t smem_u32(const void* p) {
    uint32_t a;
    asm("{ .reg .u64 t; cvta.to.shared.u64 t, %1; cvt.u32.u64 %0, t; }"
        : "=r"(a) : "l"(p));
    return a;
}
__device__ __forceinline__ void cp16(uint32_t dst, const void* src) {
    asm volatile("cp.async.cg.shared.global [%0], [%1], 16;"
                 :: "r"(dst), "l"(src) : "memory");
}
__device__ __forceinline__ void ldsm4(uint32_t* r, uint32_t addr) {
    asm volatile("ldmatrix.sync.aligned.m8n8.x4.shared.b16 {%0,%1,%2,%3}, [%4];"
                 : "=r"(r[0]), "=r"(r[1]), "=r"(r[2]), "=r"(r[3]) : "r"(addr));
}
__device__ __forceinline__ void mma16816(float* c, const uint32_t* a,
                                         uint32_t b0, uint32_t b1) {
    asm volatile(
        "mma.sync.aligned.m16n8k16.row.col.f32.bf16.bf16.f32 "
        "{%0,%1,%2,%3}, {%4,%5,%6,%7}, {%8,%9}, {%0,%1,%2,%3};"
        : "+f"(c[0]), "+f"(c[1]), "+f"(c[2]), "+f"(c[3])
        : "r"(a[0]), "r"(a[1]), "r"(a[2]), "r"(a[3]), "r"(b0), "r"(b1));
}
// 64-byte-row swizzle (rows of 64B): XOR bits[5:4] with bits[8:7]
__device__ __forceinline__ uint32_t swz64(uint32_t off) {
    return off ^ ((off >> 3) & 0x30);
}
__device__ __forceinline__ uint32_t packbf2(__nv_bfloat16 a, __nv_bfloat16 b) {
    __nv_bfloat162 t; t.x = a; t.y = b;
    return *(uint32_t*)&t;
}

// ------------------------------------------------------------ split kernels
__global__ void splitA_kernel(const float* __restrict__ z)
{
    int i = blockIdx.x * 256 + threadIdx.x;     // over MDIM*128
    int m = i >> 7, kc = (i & 127) << 2;
    float4 v = *(const float4*)(z + (size_t)m * KDIM + kc);
    __nv_bfloat16 h0 = __float2bfloat16(v.x), h1 = __float2bfloat16(v.y);
    __nv_bfloat16 h2 = __float2bfloat16(v.z), h3 = __float2bfloat16(v.w);
    __nv_bfloat16 l0 = __float2bfloat16(v.x - __bfloat162float(h0));
    __nv_bfloat16 l1 = __float2bfloat16(v.y - __bfloat162float(h1));
    __nv_bfloat16 l2 = __float2bfloat16(v.z - __bfloat162float(h2));
    __nv_bfloat16 l3 = __float2bfloat16(v.w - __bfloat162float(h3));
    uint2 H; H.x = packbf2(h0, h1); H.y = packbf2(h2, h3);
    uint2 L; L.x = packbf2(l0, l1); L.y = packbf2(l2, l3);
    *(uint2*)(g_Ah + (size_t)m * KDIM + kc) = H;
    *(uint2*)(g_Al + (size_t)m * KDIM + kc) = L;
}
__global__ void splitB_kernel(const float* __restrict__ cb)
{
    int i = blockIdx.x * 256 + threadIdx.x;     // over NDIM*128
    int n = i >> 7, kc = (i & 127) << 2;
    float4 v = *(const float4*)(cb + (size_t)n * KDIM + kc);
    __nv_bfloat16 h0 = __float2bfloat16(v.x), h1 = __float2bfloat16(v.y);
    __nv_bfloat16 h2 = __float2bfloat16(v.z), h3 = __float2bfloat16(v.w);
    __nv_bfloat16 l0 = __float2bfloat16(v.x - __bfloat162float(h0));
    __nv_bfloat16 l1 = __float2bfloat16(v.y - __bfloat162float(h1));
    __nv_bfloat16 l2 = __float2bfloat16(v.z - __bfloat162float(h2));
    __nv_bfloat16 l3 = __float2bfloat16(v.w - __bfloat162float(h3));
    uint2 H; H.x = packbf2(h0, h1); H.y = packbf2(h2, h3);
    uint2 L; L.x = packbf2(l0, l1); L.y = packbf2(l2, l3);
    *(uint2*)(g_Bh + (size_t)n * KDIM + kc) = H;
    *(uint2*)(g_Bl + (size_t)n * KDIM + kc) = L;
}

// ------------------------------------------------------------ row sumsq
__global__ void rowsq_kernel(const float* __restrict__ x, int K, int which)
{
    int row = blockIdx.x;
    const float* xr = x + (size_t)row * K;
    float s = 0.f;
    for (int c = threadIdx.x; c < K; c += 128) { float v = xr[c]; s += v * v; }
    #pragma unroll
    for (int o = 16; o; o >>= 1) s += __shfl_down_sync(0xffffffffu, s, o);
    __shared__ float ws[4];
    if ((threadIdx.x & 31) == 0) ws[threadIdx.x >> 5] = s;
    __syncthreads();
    if (threadIdx.x == 0) {
        float t = ws[0] + ws[1] + ws[2] + ws[3];
        if (which) g_esq[row] = t; else g_zsq[row] = t;
    }
}

__global__ void init_best_kernel(int M)
{
    int i = blockIdx.x * blockDim.x + threadIdx.x;
    if (i < M) g_best[i] = 0xFFFFFFFFFFFFFFFFull;
}

// ------------------------------------------------------------ HMMA GEMM+argmin
__global__ __launch_bounds__(256, 2)
void gemm_hmma_kernel()
{
    extern __shared__ char smem[];
    __shared__ unsigned long long sred[BM];
    __shared__ float s_esq[BN];
    const uint32_t smb = smem_u32(smem);
    const int tid = threadIdx.x;
    const int lane = tid & 31, warp = tid >> 5;
    const int m0 = blockIdx.y * BM;
    const int n0 = blockIdx.x * BN;

    // per-thread cp.async chunk descriptors: each 8KB region = 2 chunks/thread
    // chunk q: row = q>>2 (64B rows, 4 x 16B chunks), c = q&3
    uint32_t swo[2];
    const __nv_bfloat16 *sAh[2], *sAl[2], *sBh[2], *sBl[2];
    #pragma unroll
    for (int r = 0; r < 2; r++) {
        int q = tid + r * 256, row = q >> 2, c = q & 3;
        swo[r] = swz64(row * 64 + c * 16);
        sAh[r] = g_Ah + (size_t)(m0 + row) * KDIM + c * 8;
        sAl[r] = g_Al + (size_t)(m0 + row) * KDIM + c * 8;
        sBh[r] = g_Bh + (size_t)(n0 + row) * KDIM + c * 8;
        sBl[r] = g_Bl + (size_t)(n0 + row) * KDIM + c * 8;
    }

    // prologue: stages 0..STAGES-2
    #pragma unroll
    for (int s = 0; s < STAGES - 1; s++) {
        uint32_t bo = (uint32_t)s * STG;
        int k0 = s * BK;
        #pragma unroll
        for (int r = 0; r < 2; r++) {
            cp16(smb + bo + swo[r],        sAh[r] + k0);
            cp16(smb + bo + R_AL + swo[r], sAl[r] + k0);
            cp16(smb + bo + R_BH + swo[r], sBh[r] + k0);
            cp16(smb + bo + R_BL + swo[r], sBl[r] + k0);
        }
        asm volatile("cp.async.commit_group;" ::: "memory");
    }

    if (tid < BM) sred[tid] = 0xFFFFFFFFFFFFFFFFull;
    if (tid < BN) s_esq[tid] = g_esq[n0 + tid];

    float acc[4][4][4];
    #pragma unroll
    for (int i = 0; i < 4; i++)
        #pragma unroll
        for (int j = 0; j < 4; j++)
            #pragma unroll
            for (int q = 0; q < 4; q++) acc[i][j][q] = 0.f;

    const int wm = (warp & 1) * 64;       // warp row base (2 warps in M)
    const int wn = (warp >> 1) * 32;      // warp col base (4 warps in N)
    const uint32_t a_row = wm + (lane & 15);
    const uint32_t b_row = wn + (lane & 15);
    const uint32_t kchunk = (lane >> 4);  // 0/1: which 16B chunk of the k16 slice

    for (int kt = 0; kt < NKT; kt++) {
        asm volatile("cp.async.wait_group %0;" :: "n"(STAGES - 2));
        __syncthreads();

        // prefetch stage kt+STAGES-1 (overwrites buffer compute just released)
        int pf = kt + STAGES - 1;
        if (pf < NKT) {
            uint32_t bo = (uint32_t)(pf % STAGES) * STG;
            int k0 = pf * BK;
            #pragma unroll
            for (int r = 0; r < 2; r++) {
                cp16(smb + bo + swo[r],        sAh[r] + k0);
                cp16(smb + bo + R_AL + swo[r], sAl[r] + k0);
                cp16(smb + bo + R_BH + swo[r], sBh[r] + k0);
                cp16(smb + bo + R_BL + swo[r], sBl[r] + k0);
            }
        }
        asm volatile("cp.async.commit_group;" ::: "memory");

        const uint32_t sA = smb + (uint32_t)(kt % STAGES) * STG;
        #pragma unroll
        for (int kk = 0; kk < 2; kk++) {
            const uint32_t kof = (kk * 2 + kchunk) * 16;
            uint32_t aH[4][4], aL[4][4], b[2][4];
            #pragma unroll
            for (int i = 0; i < 4; i++)
                ldsm4(aH[i], sA + swz64((a_row + i * 16) * 64 + kof));
            #pragma unroll
            for (int i = 0; i < 4; i++)
                ldsm4(aL[i], sA + R_AL + swz64((a_row + i * 16) * 64 + kof));
            #pragma unroll
            for (int p = 0; p < 2; p++)
                ldsm4(b[p], sA + R_BH + swz64((b_row + p * 16) * 64 + kof));
            #pragma unroll
            for (int i = 0; i < 4; i++)
                #pragma unroll
                for (int j = 0; j < 4; j++) {
                    int p = j >> 1, h = j & 1;
                    mma16816(acc[i][j], aH[i], b[p][h], b[p][h + 2]);
                }
            #pragma unroll
            for (int i = 0; i < 4; i++)
                #pragma unroll
                for (int j = 0; j < 4; j++) {
                    int p = j >> 1, h = j & 1;
                    mma16816(acc[i][j], aL[i], b[p][h], b[p][h + 2]);
                }
            #pragma unroll
            for (int p = 0; p < 2; p++)
                ldsm4(b[p], sA + R_BL + swz64((b_row + p * 16) * 64 + kof));
            #pragma unroll
            for (int i = 0; i < 4; i++)
                #pragma unroll
                for (int j = 0; j < 4; j++) {
                    int p = j >> 1, h = j & 1;
                    mma16816(acc[i][j], aH[i], b[p][h], b[p][h + 2]);
                }
        }
    }

    // ---- epilogue: dist = (zsq+esq) - 2*acc, fused per-row argmin
    const int r0 = lane >> 2;
    #pragma unroll
    for (int i = 0; i < 4; i++) {
        int rowa = wm + i * 16 + r0;
        float zs0 = g_zsq[m0 + rowa];
        float zs1 = g_zsq[m0 + rowa + 8];
        unsigned long long bk0 = 0xFFFFFFFFFFFFFFFFull;
        unsigned long long bk1 = 0xFFFFFFFFFFFFFFFFull;
        #pragma unroll
        for (int j = 0; j < 4; j++) {
            int ncol = wn + j * 8 + 2 * (lane & 3);
            float e0 = s_esq[ncol], e1 = s_esq[ncol + 1];
            unsigned gn0 = (unsigned)(n0 + ncol), gn1 = gn0 + 1;
            float d;
            unsigned u;
            unsigned long long k;
            d = (zs0 + e0) - 2.0f * acc[i][j][0];
            u = __float_as_uint(d); u = (u & 0x80000000u) ? ~u : (u | 0x80000000u);
            k = ((unsigned long long)u << 32) | gn0; if (k < bk0) bk0 = k;
            d = (zs0 + e1) - 2.0f * acc[i][j][1];
            u = __float_as_uint(d); u = (u & 0x80000000u) ? ~u : (u | 0x80000000u);
            k = ((unsigned long long)u << 32) | gn1; if (k < bk0) bk0 = k;
            d = (zs1 + e0) - 2.0f * acc[i][j][2];
            u = __float_as_uint(d); u = (u & 0x80000000u) ? ~u : (u | 0x80000000u);
            k = ((unsigned long long)u << 32) | gn0; if (k < bk1) bk1 = k;
            d = (zs1 + e1) - 2.0f * acc[i][j][3];
            u = __float_as_uint(d); u = (u & 0x80000000u) ? ~u : (u | 0x80000000u);
            k = ((unsigned long long)u << 32) | gn1; if (k < bk1) bk1 = k;
        }
        // reduce across the 4 lanes sharing this row
        #pragma unroll
        for (int o = 1; o <= 2; o <<= 1) {
            unsigned long long t0 = __shfl_xor_sync(0xffffffffu, bk0, o);
            unsigned long long t1 = __shfl_xor_sync(0xffffffffu, bk1, o);
            if (t0 < bk0) bk0 = t0;
            if (t1 < bk1) bk1 = t1;
        }
        if ((lane & 3) == 0) {
            atomicMin(&sred[rowa], bk0);
            atomicMin(&sred[rowa + 8], bk1);
        }
    }
    __syncthreads();
    if (tid < BM) atomicMin(&g_best[m0 + tid], sred[tid]);
}

// ------------------------------------------------------------ gather + loss
__global__ void gather_loss_kernel(const float* __restrict__ z,
                                   const float* __restrict__ cb,
                                   float* __restrict__ out_q,
                                   float* __restrict__ out_idx)
{
    int m = blockIdx.x;
    unsigned int idx = (unsigned int)(g_best[m] & 0xFFFFFFFFu);
    const float4* zr = (const float4*)(z + (size_t)m * KDIM);
    const float4* cr = (const float4*)(cb + (size_t)idx * KDIM);
    float4* qr = (float4*)(out_q + (size_t)m * KDIM);
    float4 ze = zr[threadIdx.x];
    float4 cq = cr[threadIdx.x];
    float d0 = cq.x - ze.x, d1 = cq.y - ze.y, d2 = cq.z - ze.z, d3 = cq.w - ze.w;
    float4 o;
    o.x = ze.x + d0; o.y = ze.y + d1; o.z = ze.z + d2; o.w = ze.w + d3;
    qr[threadIdx.x] = o;
    float s = d0 * d0 + d1 * d1 + d2 * d2 + d3 * d3;
    #pragma unroll
    for (int off = 16; off; off >>= 1) s += __shfl_down_sync(0xffffffffu, s, off);
    __shared__ float ws[4];
    if ((threadIdx.x & 31) == 0) ws[threadIdx.x >> 5] = s;
    __syncthreads();
    if (threadIdx.x == 0) {
        g_partials[m] = ws[0] + ws[1] + ws[2] + ws[3];
        out_idx[m] = (float)idx;
    }
}

__global__ void loss_kernel(float* __restrict__ out_loss, int M, int K)
{
    __shared__ float sm[1024];
    float s = 0.f;
    for (int i = threadIdx.x; i < M; i += 1024) s += g_partials[i];
    sm[threadIdx.x] = s;
    __syncthreads();
    for (int o = 512; o; o >>= 1) {
        if (threadIdx.x < o) sm[threadIdx.x] += sm[threadIdx.x + o];
        __syncthreads();
    }
    if (threadIdx.x == 0) {
        float mean = sm[0] / ((float)M * (float)K);
        out_loss[0] = (mean + 0.25f * mean) / (float)K;
    }
}

// ------------------------------------------------------------ launch
extern "C" void kernel_launch(void* const* d_in, const int* in_sizes, int n_in,
                              void* d_out, int out_size)
{
    const float* z  = (const float*)d_in[0];
    const float* cb = (const float*)d_in[1];
    const int M = in_sizes[0] / KDIM;   // 32768
    const int N = in_sizes[1] / KDIM;   // 8192

    float* out      = (float*)d_out;
    float* out_q    = out;
    float* out_idx  = out + (size_t)M * KDIM;
    float* out_loss = out_idx + M;

    static int attr_done = 0;
    if (!attr_done) {
        cudaFuncSetAttribute(gemm_hmma_kernel,
                             cudaFuncAttributeMaxDynamicSharedMemorySize,
                             SMEM_DYN);
        attr_done = 1;
    }

    splitA_kernel<<<M * 128 / 256, 256>>>(z);
    splitB_kernel<<<N * 128 / 256, 256>>>(cb);
    rowsq_kernel<<<M, 128>>>(z, KDIM, 0);
    rowsq_kernel<<<N, 128>>>(cb, KDIM, 1);
    init_best_kernel<<<(M + 255) / 256, 256>>>(M);

    dim3 grid(N / BN, M / BM);
    gemm_hmma_kernel<<<grid, 256, SMEM_DYN>>>();

    gather_loss_kernel<<<M, 128>>>(z, cb, out_q, out_idx);
    loss_kernel<<<1, 1024>>>(out_loss, M, KDIM);
}